// round 16
// baseline (speedup 1.0000x reference)
#include <cuda_runtime.h>
#include <cuda_bf16.h>
#include <math.h>
#include <stdint.h>

// Problem constants
#define BATCH 2
#define SEQ   2048
#define DMODEL 1024
#define NHEAD 16
#define DKH   64
#define MROWS (BATCH * SEQ)   // 4096

// scale folded into Q projection: 1/sqrt(64) * log2(e)
#define QSCALE 0.18033688011112042f

// ---------------- scratch (device globals, no allocation) ----------------
__device__ __nv_bfloat16 g_ah[MROWS * DMODEL];
__device__ __nv_bfloat16 g_al[MROWS * DMODEL];
__device__ __nv_bfloat16 g_bh[MROWS * DMODEL];
__device__ __nv_bfloat16 g_bl[MROWS * DMODEL];
__device__ __nv_bfloat16 g_ch[MROWS * DMODEL];
__device__ __nv_bfloat16 g_cl[MROWS * DMODEL];
__device__ __nv_bfloat16 g_qh[MROWS * DMODEL];
__device__ __nv_bfloat16 g_ql[MROWS * DMODEL];
__device__ __nv_bfloat16 g_kh[MROWS * DMODEL];
__device__ __nv_bfloat16 g_kl[MROWS * DMODEL];
__device__ __nv_bfloat16 g_vh[MROWS * DMODEL];
__device__ __nv_bfloat16 g_vl[MROWS * DMODEL];
__device__ __nv_bfloat16 g_wh[4][DMODEL * DMODEL];
__device__ __nv_bfloat16 g_wl[4][DMODEL * DMODEL];

// ================= small helpers ==========================================
__device__ __forceinline__ uint32_t smem_u32(const void* p) {
    return (uint32_t)__cvta_generic_to_shared(p);
}

__device__ __forceinline__ void ldsm_x4(uint32_t* r, uint32_t saddr) {
    asm volatile(
        "ldmatrix.sync.aligned.m8n8.x4.shared.b16 {%0,%1,%2,%3}, [%4];"
        : "=r"(r[0]), "=r"(r[1]), "=r"(r[2]), "=r"(r[3]) : "r"(saddr));
}

__device__ __forceinline__ void ldsm_x4_t(uint32_t* r, uint32_t saddr) {
    asm volatile(
        "ldmatrix.sync.aligned.m8n8.x4.trans.shared.b16 {%0,%1,%2,%3}, [%4];"
        : "=r"(r[0]), "=r"(r[1]), "=r"(r[2]), "=r"(r[3]) : "r"(saddr));
}

__device__ __forceinline__ void mma16816(float* d, const uint32_t* a,
                                         const uint32_t* b) {
    asm volatile(
        "mma.sync.aligned.m16n8k16.row.col.f32.bf16.bf16.f32 "
        "{%0,%1,%2,%3}, {%4,%5,%6,%7}, {%8,%9}, {%0,%1,%2,%3};"
        : "+f"(d[0]), "+f"(d[1]), "+f"(d[2]), "+f"(d[3])
        : "r"(a[0]), "r"(a[1]), "r"(a[2]), "r"(a[3]), "r"(b[0]), "r"(b[1]));
}

__device__ __forceinline__ void cpasync16(uint32_t s, const void* g) {
    asm volatile("cp.async.cg.shared.global [%0], [%1], 16;"
                 :: "r"(s), "l"(g));
}

// pack two fp32 -> bf16x2 (hi) + residual bf16x2
__device__ __forceinline__ void split_pack(float x0, float x1,
                                           uint32_t& hp, uint32_t& lp) {
    asm("cvt.rn.bf16x2.f32 %0, %1, %2;" : "=r"(hp) : "f"(x1), "f"(x0));
    float f0 = __uint_as_float(hp << 16);
    float f1 = __uint_as_float(hp & 0xffff0000u);
    asm("cvt.rn.bf16x2.f32 %0, %1, %2;" : "=r"(lp)
        : "f"(x1 - f1), "f"(x0 - f0));
}

// ================= fp32 -> (bf16 hi, bf16 lo) split conversions ===========
__device__ __forceinline__ void cvt_body(const float4* __restrict__ x,
                                         uint2* __restrict__ hi,
                                         uint2* __restrict__ lo, int i) {
    float4 v = x[i];
    float a[4] = {v.x, v.y, v.z, v.w};
    union { __nv_bfloat16 b[4]; uint2 u; } H, L;
    #pragma unroll
    for (int j = 0; j < 4; j++) {
        __nv_bfloat16 h = __float2bfloat16(a[j]);
        float r = a[j] - __bfloat162float(h);
        H.b[j] = h;
        L.b[j] = __float2bfloat16(r);
    }
    hi[i] = H.u;
    lo[i] = L.u;
}

// single launch: y=0..2 -> q/k/v activations (nA4), y=3..6 -> weights (nW4)
__global__ void cvt_split_all(const float4* __restrict__ q,
                              const float4* __restrict__ k,
                              const float4* __restrict__ v,
                              const float4* __restrict__ w0,
                              const float4* __restrict__ w1,
                              const float4* __restrict__ w2,
                              const float4* __restrict__ w3,
                              uint2* ah, uint2* al, uint2* bh, uint2* bl,
                              uint2* ch, uint2* cl, uint2* wh, uint2* wl,
                              int nA4, int nW4) {
    const int i = blockIdx.x * blockDim.x + threadIdx.x;
    const int y = blockIdx.y;
    if (y < 3) {
        if (i >= nA4) return;
        if (y == 0)      cvt_body(q, ah, al, i);
        else if (y == 1) cvt_body(k, bh, bl, i);
        else             cvt_body(v, ch, cl, i);
    } else {
        if (i >= nW4) return;
        const int z = y - 3;
        const float4* src = (z == 0) ? w0 : (z == 1) ? w1 : (z == 2) ? w2 : w3;
        cvt_body(src, wh + (size_t)z * nW4, wl + (size_t)z * nW4, i);
    }
}

// ================= shared GEMM core: C[M,N] = A[M,K] @ W[N,K]^T ===========
// bf16x3: C = Ah*Wh + Ah*Wl + Al*Wh, fp32 accum.
// 256x128 CTA tile (8 warps x 32x128), BK=32, 2-stage cp.async,
// ONE barrier per K-chunk. 1 CTA/SM but SAME wave count as the 128x128
// config; per-output LDGSTS drops 25% (W amortized over 2x rows).
#define BKG 32
#define NCH (DMODEL / BKG)   // 32 chunks
#define RSB 80
#define TILE_A (256 * RSB)   // 20480 (Ah or Al)
#define TILE_W (128 * RSB)   // 10240 (Wh or Wl)
#define STAGEB (2 * TILE_A + 2 * TILE_W)  // 61440
#define GSMEM (2 * STAGEB)   // 122880 -> 1 CTA/SM

__device__ __forceinline__
void gemm_core(const __nv_bfloat16* __restrict__ Ah,
               const __nv_bfloat16* __restrict__ Al,
               const __nv_bfloat16* __restrict__ Wh,
               const __nv_bfloat16* __restrict__ Wl,
               float* __restrict__ Cf,
               __nv_bfloat16* __restrict__ Ch,
               __nv_bfloat16* __restrict__ Cl,
               float osc, char* smc) {
    const uint32_t sb = smem_u32(smc);
    const int tid = threadIdx.x;
    const int lane = tid & 31;
    const int wid = tid >> 5;        // warp 0..7 -> 32-row slice
    const int m0 = blockIdx.y * 256;
    const int n0 = blockIdx.x * 128;

#define LOAD_STAGE(c, buf) do {                                              \
    const uint32_t sbase = sb + (buf) * STAGEB;                              \
    const int kc = (c) * BKG;                                                \
    _Pragma("unroll")                                                        \
    for (int i = tid; i < 1024; i += 256) {                                  \
        const int r = i >> 2;                                                \
        const int g = i & 3;                                                 \
        const size_t arow = (size_t)(m0 + r) * DMODEL + kc + g * 8;          \
        const uint32_t so = r * RSB + g * 16;                                \
        cpasync16(sbase + so, Ah + arow);                                    \
        cpasync16(sbase + TILE_A + so, Al + arow);                           \
    }                                                                        \
    _Pragma("unroll")                                                        \
    for (int i = tid; i < 512; i += 256) {                                   \
        const int r = i >> 2;                                                \
        const int g = i & 3;                                                 \
        const size_t brow = (size_t)(n0 + r) * DMODEL + kc + g * 8;          \
        const uint32_t so = r * RSB + g * 16;                                \
        cpasync16(sbase + 2 * TILE_A + so, Wh + brow);                       \
        cpasync16(sbase + 2 * TILE_A + TILE_W + so, Wl + brow);              \
    }                                                                        \
    asm volatile("cp.async.commit_group;" ::: "memory");                     \
} while (0)

    float acc[2][16][4];
    #pragma unroll
    for (int mt = 0; mt < 2; mt++)
        #pragma unroll
        for (int nt = 0; nt < 16; nt++)
            #pragma unroll
            for (int q = 0; q < 4; q++) acc[mt][nt][q] = 0.0f;

    const int arow = (lane & 7) + ((lane >> 3) & 1) * 8;
    const int akh  = (lane >> 4) * 16;
    const int brow = (lane & 7) + ((lane >> 4) & 1) * 8;
    const int bkh  = ((lane >> 3) & 1) * 16;

    LOAD_STAGE(0, 0);

    for (int c = 0; c < NCH; c++) {
        const int buf = c & 1;
        asm volatile("cp.async.wait_group 0;" ::: "memory");
        __syncthreads();
        if (c + 1 < NCH) {
            LOAD_STAGE(c + 1, (c + 1) & 1);  // overwrites stage c-1's buffer
        }

        const uint32_t sAh = sb + buf * STAGEB;
        const uint32_t sAl = sAh + TILE_A;
        const uint32_t sWh = sAh + 2 * TILE_A;
        const uint32_t sWl = sWh + TILE_W;

        #pragma unroll
        for (int ks = 0; ks < 2; ks++) {
            uint32_t a_h[2][4], a_l[2][4];
            #pragma unroll
            for (int mt = 0; mt < 2; mt++) {
                const uint32_t ao =
                    (uint32_t)((wid * 32 + mt * 16 + arow) * RSB + ks * 32 + akh);
                ldsm_x4(a_h[mt], sAh + ao);
                ldsm_x4(a_l[mt], sAl + ao);
            }
            #pragma unroll
            for (int ntp = 0; ntp < 8; ntp++) {
                uint32_t bh[4], bl[4];
                const uint32_t bo =
                    (uint32_t)((ntp * 16 + brow) * RSB + ks * 32 + bkh);
                ldsm_x4(bh, sWh + bo);
                ldsm_x4(bl, sWl + bo);
                #pragma unroll
                for (int hf = 0; hf < 2; hf++)
                    #pragma unroll
                    for (int mt = 0; mt < 2; mt++)
                        mma16816(acc[mt][ntp * 2 + hf], a_h[mt], bh + 2 * hf);
                #pragma unroll
                for (int hf = 0; hf < 2; hf++)
                    #pragma unroll
                    for (int mt = 0; mt < 2; mt++)
                        mma16816(acc[mt][ntp * 2 + hf], a_l[mt], bh + 2 * hf);
                #pragma unroll
                for (int hf = 0; hf < 2; hf++)
                    #pragma unroll
                    for (int mt = 0; mt < 2; mt++)
                        mma16816(acc[mt][ntp * 2 + hf], a_h[mt], bl + 2 * hf);
            }
        }
    }

    const int g = lane >> 2;
    const int cc = lane & 3;
    if (Cf != nullptr) {
        #pragma unroll
        for (int mt = 0; mt < 2; mt++) {
            #pragma unroll
            for (int nt = 0; nt < 16; nt++) {
                const int row = m0 + wid * 32 + mt * 16 + g;
                const int col = n0 + nt * 8 + cc * 2;
                float2 v0 = make_float2(acc[mt][nt][0], acc[mt][nt][1]);
                float2 v1 = make_float2(acc[mt][nt][2], acc[mt][nt][3]);
                *reinterpret_cast<float2*>(&Cf[(size_t)row * DMODEL + col]) = v0;
                *reinterpret_cast<float2*>(&Cf[(size_t)(row + 8) * DMODEL + col]) = v1;
            }
        }
    } else {
        #pragma unroll
        for (int mt = 0; mt < 2; mt++) {
            #pragma unroll
            for (int nt = 0; nt < 16; nt++) {
                const int row = m0 + wid * 32 + mt * 16 + g;
                const int col = n0 + nt * 8 + cc * 2;
                uint32_t h01, l01, h23, l23;
                split_pack(acc[mt][nt][0] * osc, acc[mt][nt][1] * osc, h01, l01);
                split_pack(acc[mt][nt][2] * osc, acc[mt][nt][3] * osc, h23, l23);
                *reinterpret_cast<uint32_t*>(&Ch[(size_t)row * DMODEL + col]) = h01;
                *reinterpret_cast<uint32_t*>(&Cl[(size_t)row * DMODEL + col]) = l01;
                *reinterpret_cast<uint32_t*>(&Ch[(size_t)(row + 8) * DMODEL + col]) = h23;
                *reinterpret_cast<uint32_t*>(&Cl[(size_t)(row + 8) * DMODEL + col]) = l23;
            }
        }
    }
#undef LOAD_STAGE
}

// Fused Q/K/V projections: blockIdx.z selects (input, weight, output)
__global__ __launch_bounds__(256)
void mma_gemm_qkv(const __nv_bfloat16* __restrict__ ah,
                  const __nv_bfloat16* __restrict__ al,
                  const __nv_bfloat16* __restrict__ bh,
                  const __nv_bfloat16* __restrict__ bl,
                  const __nv_bfloat16* __restrict__ ch,
                  const __nv_bfloat16* __restrict__ cl,
                  const __nv_bfloat16* __restrict__ wh,
                  const __nv_bfloat16* __restrict__ wl,
                  __nv_bfloat16* __restrict__ qh,
                  __nv_bfloat16* __restrict__ ql,
                  __nv_bfloat16* __restrict__ kh,
                  __nv_bfloat16* __restrict__ kl,
                  __nv_bfloat16* __restrict__ vh,
                  __nv_bfloat16* __restrict__ vl) {
    extern __shared__ char smc[];
    const size_t WN = (size_t)DMODEL * DMODEL;
    const int z = blockIdx.z;
    const __nv_bfloat16 *Ah, *Al, *Ch, *Cl;
    float osc;
    if (z == 0)      { Ah = ah; Al = al; Ch = qh; Cl = ql; osc = QSCALE; }
    else if (z == 1) { Ah = bh; Al = bl; Ch = kh; Cl = kl; osc = 1.0f; }
    else             { Ah = ch; Al = cl; Ch = vh; Cl = vl; osc = 1.0f; }
    gemm_core(Ah, Al, wh + z * WN, wl + z * WN, nullptr,
              (__nv_bfloat16*)Ch, (__nv_bfloat16*)Cl, osc, smc);
}

// Single GEMM (output projection)
__global__ __launch_bounds__(256)
void mma_gemm_bt(const __nv_bfloat16* __restrict__ Ah,
                 const __nv_bfloat16* __restrict__ Al,
                 const __nv_bfloat16* __restrict__ Wh,
                 const __nv_bfloat16* __restrict__ Wl,
                 float* __restrict__ Cf) {
    extern __shared__ char smc[];
    gemm_core(Ah, Al, Wh, Wl, Cf, nullptr, nullptr, 1.0f, smc);
}

// ================= mma.sync flash attention (causal, bf16x3) ==============
// R10/R15 configuration VERBATIM (best measured): 128 q-rows, 256 threads,
// 1 CTA/SM, hoisted Q fragments, 3-slot KV ring, ONE barrier per KV tile,
// prefetch depth 2.
#define RSF 144
#define FS_QH 0
#define FS_QL (128 * RSF)
#define FS_KV0 (2 * 128 * RSF)           // 36864
#define KVT (64 * RSF)
#define FSTAGE (4 * KVT)                 // 36864
#define FLASH_SMEM (FS_KV0 + 3 * FSTAGE) // 147456

__global__ __launch_bounds__(256, 1)
void flash_mma_kernel(const __nv_bfloat16* __restrict__ Qh,
                      const __nv_bfloat16* __restrict__ Ql,
                      const __nv_bfloat16* __restrict__ Kh,
                      const __nv_bfloat16* __restrict__ Kl,
                      const __nv_bfloat16* __restrict__ Vh,
                      const __nv_bfloat16* __restrict__ Vl,
                      __nv_bfloat16* __restrict__ Oh,
                      __nv_bfloat16* __restrict__ Ol) {
    extern __shared__ char sm8[];
    const uint32_t sb = smem_u32(sm8);
    const int tid = threadIdx.x;
    const int lane = tid & 31;
    const int wm = tid >> 5;
    const int qi = (int)gridDim.x - 1 - (int)blockIdx.x;
    const int h = blockIdx.y;
    const int b = blockIdx.z;
    const int nkt = 2 * qi + 2;   // always >= 2
    const size_t hoff = (size_t)h * DKH;

#define LOAD_KV(kt, sloti) do {                                              \
    const int r_ = tid >> 2;                                                 \
    const int g0_ = tid & 3;                                                 \
    const size_t grow_ =                                                     \
        (size_t)(b * SEQ + (kt) * 64 + r_) * DMODEL + hoff;                  \
    const uint32_t sbase_ = sb + FS_KV0 + (sloti) * FSTAGE;                  \
    _Pragma("unroll")                                                        \
    for (int gg = 0; gg < 2; gg++) {                                         \
        const int g_ = g0_ + gg * 4;                                         \
        const uint32_t so_ = r_ * RSF + g_ * 16;                             \
        cpasync16(sbase_ + 0 * KVT + so_, Kh + grow_ + g_ * 8);              \
        cpasync16(sbase_ + 1 * KVT + so_, Kl + grow_ + g_ * 8);              \
        cpasync16(sbase_ + 2 * KVT + so_, Vh + grow_ + g_ * 8);              \
        cpasync16(sbase_ + 3 * KVT + so_, Vl + grow_ + g_ * 8);              \
    }                                                                        \
    asm volatile("cp.async.commit_group;" ::: "memory");                     \
} while (0)

    // prologue: group0 = {Q tile, KV0}; group1 = {KV1} (nkt >= 2 always)
    {
        const int r = tid >> 1;
        const int g0 = (tid & 1) * 4;
        const size_t grow = (size_t)(b * SEQ + qi * 128 + r) * DMODEL + hoff;
        #pragma unroll
        for (int gg = 0; gg < 4; gg++) {
            const int g = g0 + gg;
            const uint32_t so = r * RSF + g * 16;
            cpasync16(sb + FS_QH + so, Qh + grow + g * 8);
            cpasync16(sb + FS_QL + so, Ql + grow + g * 8);
        }
    }
    LOAD_KV(0, 0);
    LOAD_KV(1, 1);

    float m0 = -1e30f, m1 = -1e30f, l0 = 0.0f, l1 = 0.0f;
    float o[8][4];
    #pragma unroll
    for (int f = 0; f < 8; f++)
        #pragma unroll
        for (int q = 0; q < 4; q++) o[f][q] = 0.0f;

    uint32_t qhf[4][4], qlf[4][4];

    const int ar = lane & 15;
    const int ac = (lane >> 4) * 16;
    const int br = (lane & 7) + ((lane >> 4) & 1) * 8;
    const int bk = ((lane >> 3) & 1) * 16;

    int slot = 0;        // slot of stage kt (kt % 3)
    int nslot = 2;       // slot for stage kt+2
    for (int kt = 0; kt < nkt; kt++) {
        // stage kt arrived when <=1 newer group outstanding (commit order)
        if (kt + 1 < nkt) {
            asm volatile("cp.async.wait_group 1;" ::: "memory");
        } else {
            asm volatile("cp.async.wait_group 0;" ::: "memory");
        }
        __syncthreads();  // stage kt visible; all done reading slot(kt-1)

        if (kt + 2 < nkt) {
            LOAD_KV(kt + 2, nslot);   // nslot == slot(kt-1): safe post-barrier
        }

        if (kt == 0) {
            #pragma unroll
            for (int ks = 0; ks < 4; ks++) {
                const uint32_t qa =
                    sb + FS_QH + (wm * 16 + ar) * RSF + ks * 32 + ac;
                ldsm_x4(qhf[ks], qa);
                ldsm_x4(qlf[ks], qa + (FS_QL - FS_QH));
            }
        }

        const uint32_t sK = sb + FS_KV0 + slot * FSTAGE;
        const uint32_t sV = sK + 2 * KVT;

        // ---- S = Qs @ K^T (bf16x3) ----
        float s[8][4];
        #pragma unroll
        for (int f = 0; f < 8; f++)
            #pragma unroll
            for (int q = 0; q < 4; q++) s[f][q] = 0.0f;

        #pragma unroll
        for (int ks = 0; ks < 4; ks++) {
            #pragma unroll
            for (int np = 0; np < 4; np++) {
                uint32_t kbh[4], kbl[4];
                const uint32_t ka = sK + (np * 16 + br) * RSF + ks * 32 + bk;
                ldsm_x4(kbh, ka);
                ldsm_x4(kbl, ka + KVT);
                #pragma unroll
                for (int hf = 0; hf < 2; hf++)
                    mma16816(s[np * 2 + hf], qhf[ks], kbh + 2 * hf);
                #pragma unroll
                for (int hf = 0; hf < 2; hf++)
                    mma16816(s[np * 2 + hf], qhf[ks], kbl + 2 * hf);
                #pragma unroll
                for (int hf = 0; hf < 2; hf++)
                    mma16816(s[np * 2 + hf], qlf[ks], kbh + 2 * hf);
            }
        }

        // ---- causal mask (diagonal tiles only) ----
        if (kt >= 2 * qi) {
            const int grow = qi * 128 + wm * 16 + (lane >> 2);
            const int gc = kt * 64 + (lane & 3) * 2;
            #pragma unroll
            for (int f = 0; f < 8; f++) {
                const int c = gc + f * 8;
                if (c > grow)         s[f][0] = -1e30f;
                if (c + 1 > grow)     s[f][1] = -1e30f;
                if (c > grow + 8)     s[f][2] = -1e30f;
                if (c + 1 > grow + 8) s[f][3] = -1e30f;
            }
        }

        // ---- online softmax (exp2 domain; scale folded into Q) ----
        float mx0 = -1e30f, mx1 = -1e30f;
        #pragma unroll
        for (int f = 0; f < 8; f++) {
            mx0 = fmaxf(mx0, fmaxf(s[f][0], s[f][1]));
            mx1 = fmaxf(mx1, fmaxf(s[f][2], s[f][3]));
        }
        mx0 = fmaxf(mx0, __shfl_xor_sync(0xffffffffu, mx0, 1));
        mx0 = fmaxf(mx0, __shfl_xor_sync(0xffffffffu, mx0, 2));
        mx1 = fmaxf(mx1, __shfl_xor_sync(0xffffffffu, mx1, 1));
        mx1 = fmaxf(mx1, __shfl_xor_sync(0xffffffffu, mx1, 2));

        const float nm0 = fmaxf(m0, mx0);
        const float nm1 = fmaxf(m1, mx1);
        const float c0 = exp2f(m0 - nm0);
        const float c1 = exp2f(m1 - nm1);
        float r0 = 0.0f, r1 = 0.0f;
        #pragma unroll
        for (int f = 0; f < 8; f++) {
            s[f][0] = exp2f(s[f][0] - nm0);
            s[f][1] = exp2f(s[f][1] - nm0);
            s[f][2] = exp2f(s[f][2] - nm1);
            s[f][3] = exp2f(s[f][3] - nm1);
            r0 += s[f][0] + s[f][1];
            r1 += s[f][2] + s[f][3];
        }
        r0 += __shfl_xor_sync(0xffffffffu, r0, 1);
        r0 += __shfl_xor_sync(0xffffffffu, r0, 2);
        r1 += __shfl_xor_sync(0xffffffffu, r1, 1);
        r1 += __shfl_xor_sync(0xffffffffu, r1, 2);
        l0 = l0 * c0 + r0;  m0 = nm0;
        l1 = l1 * c1 + r1;  m1 = nm1;
        #pragma unroll
        for (int f = 0; f < 8; f++) {
            o[f][0] *= c0; o[f][1] *= c0;
            o[f][2] *= c1; o[f][3] *= c1;
        }

        // ---- pack P into A-fragments (hi + residual) ----
        uint32_t ph[4][4], pl[4][4];
        #pragma unroll
        for (int j = 0; j < 4; j++) {
            split_pack(s[2 * j][0],     s[2 * j][1],     ph[j][0], pl[j][0]);
            split_pack(s[2 * j][2],     s[2 * j][3],     ph[j][1], pl[j][1]);
            split_pack(s[2 * j + 1][0], s[2 * j + 1][1], ph[j][2], pl[j][2]);
            split_pack(s[2 * j + 1][2], s[2 * j + 1][3], ph[j][3], pl[j][3]);
        }

        // ---- O += P @ V (bf16x3, V via trans ldmatrix) ----
        #pragma unroll
        for (int ks = 0; ks < 4; ks++) {
            #pragma unroll
            for (int np = 0; np < 4; np++) {
                uint32_t vbh[4], vbl[4];
                const uint32_t va = sV + (ks * 16 + ar) * RSF + np * 32 + ac;
                ldsm_x4_t(vbh, va);
                ldsm_x4_t(vbl, va + KVT);
                #pragma unroll
                for (int hf = 0; hf < 2; hf++)
                    mma16816(o[np * 2 + hf], ph[ks], vbh + 2 * hf);
                #pragma unroll
                for (int hf = 0; hf < 2; hf++)
                    mma16816(o[np * 2 + hf], ph[ks], vbl + 2 * hf);
                #pragma unroll
                for (int hf = 0; hf < 2; hf++)
                    mma16816(o[np * 2 + hf], pl[ks], vbh + 2 * hf);
            }
        }

        // advance ring: slot(kt+1), slot(kt+3)
        slot = (slot + 1 > 2) ? 0 : (slot + 1);
        nslot = (nslot + 1 > 2) ? 0 : (nslot + 1);
    }

    // ---- epilogue: normalize, split to bf16 hi/lo, store ----
    const float i0 = 1.0f / l0;
    const float i1 = 1.0f / l1;
    const size_t row0 = (size_t)(b * SEQ + qi * 128 + wm * 16 + (lane >> 2));
    const int colb = (int)hoff + (lane & 3) * 2;
    #pragma unroll
    for (int f = 0; f < 8; f++) {
        const size_t off0 = row0 * DMODEL + colb + f * 8;
        const size_t off1 = (row0 + 8) * DMODEL + colb + f * 8;
        uint32_t h01, l01, h23, l23;
        split_pack(o[f][0] * i0, o[f][1] * i0, h01, l01);
        split_pack(o[f][2] * i1, o[f][3] * i1, h23, l23);
        *reinterpret_cast<uint32_t*>(&Oh[off0]) = h01;
        *reinterpret_cast<uint32_t*>(&Ol[off0]) = l01;
        *reinterpret_cast<uint32_t*>(&Oh[off1]) = h23;
        *reinterpret_cast<uint32_t*>(&Ol[off1]) = l23;
    }
#undef LOAD_KV
}

// ---------------- launch --------------------------------------------------
extern "C" void kernel_launch(void* const* d_in, const int* in_sizes, int n_in,
                              void* d_out, int out_size) {
    const float* q   = (const float*)d_in[0];
    const float* k   = (const float*)d_in[1];
    const float* v   = (const float*)d_in[2];
    // d_in[3] = mask (deterministic causal tril) — handled analytically
    const float* w_q = (const float*)d_in[4];
    const float* w_k = (const float*)d_in[5];
    const float* w_v = (const float*)d_in[6];
    const float* w_o = (const float*)d_in[7];
    float* out = (float*)d_out;

    __nv_bfloat16 *ah, *al, *bh, *bl, *ch, *cl;
    __nv_bfloat16 *qh, *ql, *kh, *kl, *vh, *vl, *wh, *wl;
    cudaGetSymbolAddress((void**)&ah, g_ah);
    cudaGetSymbolAddress((void**)&al, g_al);
    cudaGetSymbolAddress((void**)&bh, g_bh);
    cudaGetSymbolAddress((void**)&bl, g_bl);
    cudaGetSymbolAddress((void**)&ch, g_ch);
    cudaGetSymbolAddress((void**)&cl, g_cl);
    cudaGetSymbolAddress((void**)&qh, g_qh);
    cudaGetSymbolAddress((void**)&ql, g_ql);
    cudaGetSymbolAddress((void**)&kh, g_kh);
    cudaGetSymbolAddress((void**)&kl, g_kl);
    cudaGetSymbolAddress((void**)&vh, g_vh);
    cudaGetSymbolAddress((void**)&vl, g_vl);
    cudaGetSymbolAddress((void**)&wh, g_wh);
    cudaGetSymbolAddress((void**)&wl, g_wl);

    cudaFuncSetAttribute(mma_gemm_qkv,
                         cudaFuncAttributeMaxDynamicSharedMemorySize, GSMEM);
    cudaFuncSetAttribute(mma_gemm_bt,
                         cudaFuncAttributeMaxDynamicSharedMemorySize, GSMEM);
    cudaFuncSetAttribute(flash_mma_kernel,
                         cudaFuncAttributeMaxDynamicSharedMemorySize,
                         FLASH_SMEM);

    const int nA4 = MROWS * DMODEL / 4;   // 1048576
    const int nW4 = DMODEL * DMODEL / 4;  // 262144
    const size_t WN = (size_t)DMODEL * DMODEL;

    // all splits in ONE launch (y=0..2 acts, y=3..6 weights)
    cvt_split_all<<<dim3(nA4 / 256, 7), 256>>>(
        (const float4*)q, (const float4*)k, (const float4*)v,
        (const float4*)w_q, (const float4*)w_k, (const float4*)w_v,
        (const float4*)w_o,
        (uint2*)ah, (uint2*)al, (uint2*)bh, (uint2*)bl, (uint2*)ch, (uint2*)cl,
        (uint2*)wh, (uint2*)wl, nA4, nW4);

    // fused Q/K/V projections: 256x128 tiles
    dim3 qkvgrid(DMODEL / 128, MROWS / 256, 3);  // (8, 16, 3) = 384 CTAs
    mma_gemm_qkv<<<qkvgrid, 256, GSMEM>>>(ah, al, bh, bl, ch, cl, wh, wl,
                                          qh, ql, kh, kl, vh, vl);

    // flash attention: 128-row CTAs, 256 threads, 3-slot KV ring (best known)
    dim3 agrid(SEQ / 128, NHEAD, BATCH);  // (16, 16, 2)
    flash_mma_kernel<<<agrid, 256, FLASH_SMEM>>>(qh, ql, kh, kl, vh, vl, ah, al);

    // output projection -> fp32 out: 256x128 tiles
    dim3 ggrid(DMODEL / 128, MROWS / 256);  // (8, 16) = 128 CTAs
    mma_gemm_bt<<<ggrid, 256, GSMEM>>>(ah, al, wh + 3 * WN, wl + 3 * WN, out);
}

// round 17
// speedup vs baseline: 1.0238x; 1.0238x over previous
#include <cuda_runtime.h>
#include <cuda_bf16.h>
#include <math.h>
#include <stdint.h>

// Problem constants
#define BATCH 2
#define SEQ   2048
#define DMODEL 1024
#define NHEAD 16
#define DKH   64
#define MROWS (BATCH * SEQ)   // 4096

// scale folded into Q projection: 1/sqrt(64) * log2(e)
#define QSCALE 0.18033688011112042f

// ---------------- scratch (device globals, no allocation) ----------------
__device__ __nv_bfloat16 g_ah[MROWS * DMODEL];
__device__ __nv_bfloat16 g_al[MROWS * DMODEL];
__device__ __nv_bfloat16 g_bh[MROWS * DMODEL];
__device__ __nv_bfloat16 g_bl[MROWS * DMODEL];
__device__ __nv_bfloat16 g_ch[MROWS * DMODEL];
__device__ __nv_bfloat16 g_cl[MROWS * DMODEL];
__device__ __nv_bfloat16 g_qh[MROWS * DMODEL];
__device__ __nv_bfloat16 g_ql[MROWS * DMODEL];
__device__ __nv_bfloat16 g_kh[MROWS * DMODEL];
__device__ __nv_bfloat16 g_kl[MROWS * DMODEL];
__device__ __nv_bfloat16 g_vh[MROWS * DMODEL];
__device__ __nv_bfloat16 g_vl[MROWS * DMODEL];
__device__ __nv_bfloat16 g_wh[4][DMODEL * DMODEL];
__device__ __nv_bfloat16 g_wl[4][DMODEL * DMODEL];

// ================= small helpers ==========================================
__device__ __forceinline__ uint32_t smem_u32(const void* p) {
    return (uint32_t)__cvta_generic_to_shared(p);
}

__device__ __forceinline__ void ldsm_x4(uint32_t* r, uint32_t saddr) {
    asm volatile(
        "ldmatrix.sync.aligned.m8n8.x4.shared.b16 {%0,%1,%2,%3}, [%4];"
        : "=r"(r[0]), "=r"(r[1]), "=r"(r[2]), "=r"(r[3]) : "r"(saddr));
}

__device__ __forceinline__ void ldsm_x4_t(uint32_t* r, uint32_t saddr) {
    asm volatile(
        "ldmatrix.sync.aligned.m8n8.x4.trans.shared.b16 {%0,%1,%2,%3}, [%4];"
        : "=r"(r[0]), "=r"(r[1]), "=r"(r[2]), "=r"(r[3]) : "r"(saddr));
}

__device__ __forceinline__ void mma16816(float* d, const uint32_t* a,
                                         const uint32_t* b) {
    asm volatile(
        "mma.sync.aligned.m16n8k16.row.col.f32.bf16.bf16.f32 "
        "{%0,%1,%2,%3}, {%4,%5,%6,%7}, {%8,%9}, {%0,%1,%2,%3};"
        : "+f"(d[0]), "+f"(d[1]), "+f"(d[2]), "+f"(d[3])
        : "r"(a[0]), "r"(a[1]), "r"(a[2]), "r"(a[3]), "r"(b[0]), "r"(b[1]));
}

__device__ __forceinline__ void cpasync16(uint32_t s, const void* g) {
    asm volatile("cp.async.cg.shared.global [%0], [%1], 16;"
                 :: "r"(s), "l"(g));
}

// pack two fp32 -> bf16x2 (hi) + residual bf16x2
__device__ __forceinline__ void split_pack(float x0, float x1,
                                           uint32_t& hp, uint32_t& lp) {
    asm("cvt.rn.bf16x2.f32 %0, %1, %2;" : "=r"(hp) : "f"(x1), "f"(x0));
    float f0 = __uint_as_float(hp << 16);
    float f1 = __uint_as_float(hp & 0xffff0000u);
    asm("cvt.rn.bf16x2.f32 %0, %1, %2;" : "=r"(lp)
        : "f"(x1 - f1), "f"(x0 - f0));
}

// ================= fp32 -> (bf16 hi, bf16 lo) split conversions ===========
__device__ __forceinline__ void cvt_body(const float4* __restrict__ x,
                                         uint2* __restrict__ hi,
                                         uint2* __restrict__ lo, int i) {
    float4 v = x[i];
    float a[4] = {v.x, v.y, v.z, v.w};
    union { __nv_bfloat16 b[4]; uint2 u; } H, L;
    #pragma unroll
    for (int j = 0; j < 4; j++) {
        __nv_bfloat16 h = __float2bfloat16(a[j]);
        float r = a[j] - __bfloat162float(h);
        H.b[j] = h;
        L.b[j] = __float2bfloat16(r);
    }
    hi[i] = H.u;
    lo[i] = L.u;
}

// single launch: y=0..2 -> q/k/v activations (nA4), y=3..6 -> weights (nW4)
__global__ void cvt_split_all(const float4* __restrict__ q,
                              const float4* __restrict__ k,
                              const float4* __restrict__ v,
                              const float4* __restrict__ w0,
                              const float4* __restrict__ w1,
                              const float4* __restrict__ w2,
                              const float4* __restrict__ w3,
                              uint2* ah, uint2* al, uint2* bh, uint2* bl,
                              uint2* ch, uint2* cl, uint2* wh, uint2* wl,
                              int nA4, int nW4) {
    const int i = blockIdx.x * blockDim.x + threadIdx.x;
    const int y = blockIdx.y;
    if (y < 3) {
        if (i >= nA4) return;
        if (y == 0)      cvt_body(q, ah, al, i);
        else if (y == 1) cvt_body(k, bh, bl, i);
        else             cvt_body(v, ch, cl, i);
    } else {
        if (i >= nW4) return;
        const int z = y - 3;
        const float4* src = (z == 0) ? w0 : (z == 1) ? w1 : (z == 2) ? w2 : w3;
        cvt_body(src, wh + (size_t)z * nW4, wl + (size_t)z * nW4, i);
    }
}

// ========== GEMM core A: 128x128 tile, 2 CTAs/SM (best for QKV) ===========
// bf16x3: C = Ah*Wh + Ah*Wl + Al*Wh, fp32 accum, single barrier per chunk.
#define BKG 32
#define NCH (DMODEL / BKG)   // 32 chunks
#define RSB 80
#define TILEB (128 * RSB)
#define STAGEB (4 * TILEB)
#define GSMEM (2 * STAGEB)   // 81920 -> 2 CTAs/SM

__device__ __forceinline__
void gemm_core128(const __nv_bfloat16* __restrict__ Ah,
                  const __nv_bfloat16* __restrict__ Al,
                  const __nv_bfloat16* __restrict__ Wh,
                  const __nv_bfloat16* __restrict__ Wl,
                  __nv_bfloat16* __restrict__ Ch,
                  __nv_bfloat16* __restrict__ Cl,
                  float osc, char* smc) {
    const uint32_t sb = smem_u32(smc);
    const int tid = threadIdx.x;
    const int lane = tid & 31;
    const int wid = tid >> 5;
    const int wm = wid >> 1;
    const int wn = wid & 1;
    const int m0 = blockIdx.y * 128;
    const int n0 = blockIdx.x * 128;

    const int lr = tid >> 2;
    const int lg = tid & 3;

#define LOAD_STAGE(c, buf) do {                                              \
    const uint32_t sbase = sb + (buf) * STAGEB;                              \
    const int kc = (c) * BKG + lg * 8;                                       \
    _Pragma("unroll")                                                        \
    for (int half = 0; half < 2; half++) {                                   \
        const int r = half * 64 + lr;                                        \
        const size_t arow = (size_t)(m0 + r) * DMODEL + kc;                  \
        const size_t brow = (size_t)(n0 + r) * DMODEL + kc;                  \
        cpasync16(sbase + 0 * TILEB + r * RSB + lg * 16, Ah + arow);         \
        cpasync16(sbase + 1 * TILEB + r * RSB + lg * 16, Al + arow);         \
        cpasync16(sbase + 2 * TILEB + r * RSB + lg * 16, Wh + brow);         \
        cpasync16(sbase + 3 * TILEB + r * RSB + lg * 16, Wl + brow);         \
    }                                                                        \
    asm volatile("cp.async.commit_group;" ::: "memory");                     \
} while (0)

    float acc[2][8][4];
    #pragma unroll
    for (int mt = 0; mt < 2; mt++)
        #pragma unroll
        for (int nt = 0; nt < 8; nt++)
            #pragma unroll
            for (int q = 0; q < 4; q++) acc[mt][nt][q] = 0.0f;

    const int arow = (lane & 7) + ((lane >> 3) & 1) * 8;
    const int akh  = (lane >> 4) * 16;
    const int brow = (lane & 7) + ((lane >> 4) & 1) * 8;
    const int bkh  = ((lane >> 3) & 1) * 16;

    LOAD_STAGE(0, 0);

    for (int c = 0; c < NCH; c++) {
        const int buf = c & 1;
        asm volatile("cp.async.wait_group 0;" ::: "memory");
        __syncthreads();
        if (c + 1 < NCH) {
            LOAD_STAGE(c + 1, (c + 1) & 1);
        }

        const uint32_t sAh = sb + buf * STAGEB + 0 * TILEB;
        const uint32_t sAl = sb + buf * STAGEB + 1 * TILEB;
        const uint32_t sWh = sb + buf * STAGEB + 2 * TILEB;
        const uint32_t sWl = sb + buf * STAGEB + 3 * TILEB;

        #pragma unroll
        for (int ks = 0; ks < 2; ks++) {
            uint32_t a_h[2][4], a_l[2][4];
            #pragma unroll
            for (int mt = 0; mt < 2; mt++) {
                const uint32_t ao =
                    (uint32_t)((wm * 32 + mt * 16 + arow) * RSB + ks * 32 + akh);
                ldsm_x4(a_h[mt], sAh + ao);
                ldsm_x4(a_l[mt], sAl + ao);
            }
            #pragma unroll
            for (int ntp = 0; ntp < 4; ntp++) {
                uint32_t bh[4], bl[4];
                const uint32_t bo =
                    (uint32_t)((wn * 64 + ntp * 16 + brow) * RSB + ks * 32 + bkh);
                ldsm_x4(bh, sWh + bo);
                ldsm_x4(bl, sWl + bo);
                #pragma unroll
                for (int hf = 0; hf < 2; hf++)
                    #pragma unroll
                    for (int mt = 0; mt < 2; mt++)
                        mma16816(acc[mt][ntp * 2 + hf], a_h[mt], bh + 2 * hf);
                #pragma unroll
                for (int hf = 0; hf < 2; hf++)
                    #pragma unroll
                    for (int mt = 0; mt < 2; mt++)
                        mma16816(acc[mt][ntp * 2 + hf], a_l[mt], bh + 2 * hf);
                #pragma unroll
                for (int hf = 0; hf < 2; hf++)
                    #pragma unroll
                    for (int mt = 0; mt < 2; mt++)
                        mma16816(acc[mt][ntp * 2 + hf], a_h[mt], bl + 2 * hf);
            }
        }
    }

    const int g = lane >> 2;
    const int cc = lane & 3;
    #pragma unroll
    for (int mt = 0; mt < 2; mt++) {
        #pragma unroll
        for (int nt = 0; nt < 8; nt++) {
            const int row = m0 + wm * 32 + mt * 16 + g;
            const int col = n0 + wn * 64 + nt * 8 + cc * 2;
            uint32_t h01, l01, h23, l23;
            split_pack(acc[mt][nt][0] * osc, acc[mt][nt][1] * osc, h01, l01);
            split_pack(acc[mt][nt][2] * osc, acc[mt][nt][3] * osc, h23, l23);
            *reinterpret_cast<uint32_t*>(&Ch[(size_t)row * DMODEL + col]) = h01;
            *reinterpret_cast<uint32_t*>(&Cl[(size_t)row * DMODEL + col]) = l01;
            *reinterpret_cast<uint32_t*>(&Ch[(size_t)(row + 8) * DMODEL + col]) = h23;
            *reinterpret_cast<uint32_t*>(&Cl[(size_t)(row + 8) * DMODEL + col]) = l23;
        }
    }
#undef LOAD_STAGE
}

// Fused Q/K/V projections on the 128x128 core
__global__ __launch_bounds__(256)
void mma_gemm_qkv(const __nv_bfloat16* __restrict__ ah,
                  const __nv_bfloat16* __restrict__ al,
                  const __nv_bfloat16* __restrict__ bh,
                  const __nv_bfloat16* __restrict__ bl,
                  const __nv_bfloat16* __restrict__ ch,
                  const __nv_bfloat16* __restrict__ cl,
                  const __nv_bfloat16* __restrict__ wh,
                  const __nv_bfloat16* __restrict__ wl,
                  __nv_bfloat16* __restrict__ qh,
                  __nv_bfloat16* __restrict__ ql,
                  __nv_bfloat16* __restrict__ kh,
                  __nv_bfloat16* __restrict__ kl,
                  __nv_bfloat16* __restrict__ vh,
                  __nv_bfloat16* __restrict__ vl) {
    extern __shared__ char smc[];
    const size_t WN = (size_t)DMODEL * DMODEL;
    const int z = blockIdx.z;
    const __nv_bfloat16 *Ah, *Al, *Ch, *Cl;
    float osc;
    if (z == 0)      { Ah = ah; Al = al; Ch = qh; Cl = ql; osc = QSCALE; }
    else if (z == 1) { Ah = bh; Al = bl; Ch = kh; Cl = kl; osc = 1.0f; }
    else             { Ah = ch; Al = cl; Ch = vh; Cl = vl; osc = 1.0f; }
    gemm_core128(Ah, Al, wh + z * WN, wl + z * WN,
                 (__nv_bfloat16*)Ch, (__nv_bfloat16*)Cl, osc, smc);
}

// ========== GEMM core B: 256x128 tile, fp32 out (best for W_O) ============
#define TILE_A2 (256 * RSB)   // 20480
#define TILE_W2 (128 * RSB)   // 10240
#define STAGEB2 (2 * TILE_A2 + 2 * TILE_W2)  // 61440
#define GSMEM2 (2 * STAGEB2)  // 122880 -> 1 CTA/SM

__global__ __launch_bounds__(256)
void mma_gemm_bt(const __nv_bfloat16* __restrict__ Ah,
                 const __nv_bfloat16* __restrict__ Al,
                 const __nv_bfloat16* __restrict__ Wh,
                 const __nv_bfloat16* __restrict__ Wl,
                 float* __restrict__ Cf) {
    extern __shared__ char smc[];
    const uint32_t sb = smem_u32(smc);
    const int tid = threadIdx.x;
    const int lane = tid & 31;
    const int wid = tid >> 5;
    const int m0 = blockIdx.y * 256;
    const int n0 = blockIdx.x * 128;

#define LOAD_STAGE2(c, buf) do {                                             \
    const uint32_t sbase = sb + (buf) * STAGEB2;                             \
    const int kc = (c) * BKG;                                                \
    _Pragma("unroll")                                                        \
    for (int i = tid; i < 1024; i += 256) {                                  \
        const int r = i >> 2;                                                \
        const int g = i & 3;                                                 \
        const size_t arow = (size_t)(m0 + r) * DMODEL + kc + g * 8;          \
        const uint32_t so = r * RSB + g * 16;                                \
        cpasync16(sbase + so, Ah + arow);                                    \
        cpasync16(sbase + TILE_A2 + so, Al + arow);                          \
    }                                                                        \
    _Pragma("unroll")                                                        \
    for (int i = tid; i < 512; i += 256) {                                   \
        const int r = i >> 2;                                                \
        const int g = i & 3;                                                 \
        const size_t brow = (size_t)(n0 + r) * DMODEL + kc + g * 8;          \
        const uint32_t so = r * RSB + g * 16;                                \
        cpasync16(sbase + 2 * TILE_A2 + so, Wh + brow);                      \
        cpasync16(sbase + 2 * TILE_A2 + TILE_W2 + so, Wl + brow);            \
    }                                                                        \
    asm volatile("cp.async.commit_group;" ::: "memory");                     \
} while (0)

    float acc[2][16][4];
    #pragma unroll
    for (int mt = 0; mt < 2; mt++)
        #pragma unroll
        for (int nt = 0; nt < 16; nt++)
            #pragma unroll
            for (int q = 0; q < 4; q++) acc[mt][nt][q] = 0.0f;

    const int arow = (lane & 7) + ((lane >> 3) & 1) * 8;
    const int akh  = (lane >> 4) * 16;
    const int brow = (lane & 7) + ((lane >> 4) & 1) * 8;
    const int bkh  = ((lane >> 3) & 1) * 16;

    LOAD_STAGE2(0, 0);

    for (int c = 0; c < NCH; c++) {
        const int buf = c & 1;
        asm volatile("cp.async.wait_group 0;" ::: "memory");
        __syncthreads();
        if (c + 1 < NCH) {
            LOAD_STAGE2(c + 1, (c + 1) & 1);
        }

        const uint32_t sAh = sb + buf * STAGEB2;
        const uint32_t sAl = sAh + TILE_A2;
        const uint32_t sWh = sAh + 2 * TILE_A2;
        const uint32_t sWl = sWh + TILE_W2;

        #pragma unroll
        for (int ks = 0; ks < 2; ks++) {
            uint32_t a_h[2][4], a_l[2][4];
            #pragma unroll
            for (int mt = 0; mt < 2; mt++) {
                const uint32_t ao =
                    (uint32_t)((wid * 32 + mt * 16 + arow) * RSB + ks * 32 + akh);
                ldsm_x4(a_h[mt], sAh + ao);
                ldsm_x4(a_l[mt], sAl + ao);
            }
            #pragma unroll
            for (int ntp = 0; ntp < 8; ntp++) {
                uint32_t bh[4], bl[4];
                const uint32_t bo =
                    (uint32_t)((ntp * 16 + brow) * RSB + ks * 32 + bkh);
                ldsm_x4(bh, sWh + bo);
                ldsm_x4(bl, sWl + bo);
                #pragma unroll
                for (int hf = 0; hf < 2; hf++)
                    #pragma unroll
                    for (int mt = 0; mt < 2; mt++)
                        mma16816(acc[mt][ntp * 2 + hf], a_h[mt], bh + 2 * hf);
                #pragma unroll
                for (int hf = 0; hf < 2; hf++)
                    #pragma unroll
                    for (int mt = 0; mt < 2; mt++)
                        mma16816(acc[mt][ntp * 2 + hf], a_l[mt], bh + 2 * hf);
                #pragma unroll
                for (int hf = 0; hf < 2; hf++)
                    #pragma unroll
                    for (int mt = 0; mt < 2; mt++)
                        mma16816(acc[mt][ntp * 2 + hf], a_h[mt], bl + 2 * hf);
            }
        }
    }

    const int g = lane >> 2;
    const int cc = lane & 3;
    #pragma unroll
    for (int mt = 0; mt < 2; mt++) {
        #pragma unroll
        for (int nt = 0; nt < 16; nt++) {
            const int row = m0 + wid * 32 + mt * 16 + g;
            const int col = n0 + nt * 8 + cc * 2;
            float2 v0 = make_float2(acc[mt][nt][0], acc[mt][nt][1]);
            float2 v1 = make_float2(acc[mt][nt][2], acc[mt][nt][3]);
            *reinterpret_cast<float2*>(&Cf[(size_t)row * DMODEL + col]) = v0;
            *reinterpret_cast<float2*>(&Cf[(size_t)(row + 8) * DMODEL + col]) = v1;
        }
    }
#undef LOAD_STAGE2
}

// ================= mma.sync flash attention (causal, bf16x3) ==============
// R10/R15 configuration VERBATIM (best measured): 128 q-rows, 256 threads,
// 1 CTA/SM, hoisted Q fragments, 3-slot KV ring, ONE barrier per KV tile,
// prefetch depth 2.
#define RSF 144
#define FS_QH 0
#define FS_QL (128 * RSF)
#define FS_KV0 (2 * 128 * RSF)           // 36864
#define KVT (64 * RSF)
#define FSTAGE (4 * KVT)                 // 36864
#define FLASH_SMEM (FS_KV0 + 3 * FSTAGE) // 147456

__global__ __launch_bounds__(256, 1)
void flash_mma_kernel(const __nv_bfloat16* __restrict__ Qh,
                      const __nv_bfloat16* __restrict__ Ql,
                      const __nv_bfloat16* __restrict__ Kh,
                      const __nv_bfloat16* __restrict__ Kl,
                      const __nv_bfloat16* __restrict__ Vh,
                      const __nv_bfloat16* __restrict__ Vl,
                      __nv_bfloat16* __restrict__ Oh,
                      __nv_bfloat16* __restrict__ Ol) {
    extern __shared__ char sm8[];
    const uint32_t sb = smem_u32(sm8);
    const int tid = threadIdx.x;
    const int lane = tid & 31;
    const int wm = tid >> 5;
    const int qi = (int)gridDim.x - 1 - (int)blockIdx.x;
    const int h = blockIdx.y;
    const int b = blockIdx.z;
    const int nkt = 2 * qi + 2;   // always >= 2
    const size_t hoff = (size_t)h * DKH;

#define LOAD_KV(kt, sloti) do {                                              \
    const int r_ = tid >> 2;                                                 \
    const int g0_ = tid & 3;                                                 \
    const size_t grow_ =                                                     \
        (size_t)(b * SEQ + (kt) * 64 + r_) * DMODEL + hoff;                  \
    const uint32_t sbase_ = sb + FS_KV0 + (sloti) * FSTAGE;                  \
    _Pragma("unroll")                                                        \
    for (int gg = 0; gg < 2; gg++) {                                         \
        const int g_ = g0_ + gg * 4;                                         \
        const uint32_t so_ = r_ * RSF + g_ * 16;                             \
        cpasync16(sbase_ + 0 * KVT + so_, Kh + grow_ + g_ * 8);              \
        cpasync16(sbase_ + 1 * KVT + so_, Kl + grow_ + g_ * 8);              \
        cpasync16(sbase_ + 2 * KVT + so_, Vh + grow_ + g_ * 8);              \
        cpasync16(sbase_ + 3 * KVT + so_, Vl + grow_ + g_ * 8);              \
    }                                                                        \
    asm volatile("cp.async.commit_group;" ::: "memory");                     \
} while (0)

    // prologue: group0 = {Q tile, KV0}; group1 = {KV1} (nkt >= 2 always)
    {
        const int r = tid >> 1;
        const int g0 = (tid & 1) * 4;
        const size_t grow = (size_t)(b * SEQ + qi * 128 + r) * DMODEL + hoff;
        #pragma unroll
        for (int gg = 0; gg < 4; gg++) {
            const int g = g0 + gg;
            const uint32_t so = r * RSF + g * 16;
            cpasync16(sb + FS_QH + so, Qh + grow + g * 8);
            cpasync16(sb + FS_QL + so, Ql + grow + g * 8);
        }
    }
    LOAD_KV(0, 0);
    LOAD_KV(1, 1);

    float m0 = -1e30f, m1 = -1e30f, l0 = 0.0f, l1 = 0.0f;
    float o[8][4];
    #pragma unroll
    for (int f = 0; f < 8; f++)
        #pragma unroll
        for (int q = 0; q < 4; q++) o[f][q] = 0.0f;

    uint32_t qhf[4][4], qlf[4][4];

    const int ar = lane & 15;
    const int ac = (lane >> 4) * 16;
    const int br = (lane & 7) + ((lane >> 4) & 1) * 8;
    const int bk = ((lane >> 3) & 1) * 16;

    int slot = 0;
    int nslot = 2;
    for (int kt = 0; kt < nkt; kt++) {
        if (kt + 1 < nkt) {
            asm volatile("cp.async.wait_group 1;" ::: "memory");
        } else {
            asm volatile("cp.async.wait_group 0;" ::: "memory");
        }
        __syncthreads();

        if (kt + 2 < nkt) {
            LOAD_KV(kt + 2, nslot);
        }

        if (kt == 0) {
            #pragma unroll
            for (int ks = 0; ks < 4; ks++) {
                const uint32_t qa =
                    sb + FS_QH + (wm * 16 + ar) * RSF + ks * 32 + ac;
                ldsm_x4(qhf[ks], qa);
                ldsm_x4(qlf[ks], qa + (FS_QL - FS_QH));
            }
        }

        const uint32_t sK = sb + FS_KV0 + slot * FSTAGE;
        const uint32_t sV = sK + 2 * KVT;

        float s[8][4];
        #pragma unroll
        for (int f = 0; f < 8; f++)
            #pragma unroll
            for (int q = 0; q < 4; q++) s[f][q] = 0.0f;

        #pragma unroll
        for (int ks = 0; ks < 4; ks++) {
            #pragma unroll
            for (int np = 0; np < 4; np++) {
                uint32_t kbh[4], kbl[4];
                const uint32_t ka = sK + (np * 16 + br) * RSF + ks * 32 + bk;
                ldsm_x4(kbh, ka);
                ldsm_x4(kbl, ka + KVT);
                #pragma unroll
                for (int hf = 0; hf < 2; hf++)
                    mma16816(s[np * 2 + hf], qhf[ks], kbh + 2 * hf);
                #pragma unroll
                for (int hf = 0; hf < 2; hf++)
                    mma16816(s[np * 2 + hf], qhf[ks], kbl + 2 * hf);
                #pragma unroll
                for (int hf = 0; hf < 2; hf++)
                    mma16816(s[np * 2 + hf], qlf[ks], kbh + 2 * hf);
            }
        }

        if (kt >= 2 * qi) {
            const int grow = qi * 128 + wm * 16 + (lane >> 2);
            const int gc = kt * 64 + (lane & 3) * 2;
            #pragma unroll
            for (int f = 0; f < 8; f++) {
                const int c = gc + f * 8;
                if (c > grow)         s[f][0] = -1e30f;
                if (c + 1 > grow)     s[f][1] = -1e30f;
                if (c > grow + 8)     s[f][2] = -1e30f;
                if (c + 1 > grow + 8) s[f][3] = -1e30f;
            }
        }

        float mx0 = -1e30f, mx1 = -1e30f;
        #pragma unroll
        for (int f = 0; f < 8; f++) {
            mx0 = fmaxf(mx0, fmaxf(s[f][0], s[f][1]));
            mx1 = fmaxf(mx1, fmaxf(s[f][2], s[f][3]));
        }
        mx0 = fmaxf(mx0, __shfl_xor_sync(0xffffffffu, mx0, 1));
        mx0 = fmaxf(mx0, __shfl_xor_sync(0xffffffffu, mx0, 2));
        mx1 = fmaxf(mx1, __shfl_xor_sync(0xffffffffu, mx1, 1));
        mx1 = fmaxf(mx1, __shfl_xor_sync(0xffffffffu, mx1, 2));

        const float nm0 = fmaxf(m0, mx0);
        const float nm1 = fmaxf(m1, mx1);
        const float c0 = exp2f(m0 - nm0);
        const float c1 = exp2f(m1 - nm1);
        float r0 = 0.0f, r1 = 0.0f;
        #pragma unroll
        for (int f = 0; f < 8; f++) {
            s[f][0] = exp2f(s[f][0] - nm0);
            s[f][1] = exp2f(s[f][1] - nm0);
            s[f][2] = exp2f(s[f][2] - nm1);
            s[f][3] = exp2f(s[f][3] - nm1);
            r0 += s[f][0] + s[f][1];
            r1 += s[f][2] + s[f][3];
        }
        r0 += __shfl_xor_sync(0xffffffffu, r0, 1);
        r0 += __shfl_xor_sync(0xffffffffu, r0, 2);
        r1 += __shfl_xor_sync(0xffffffffu, r1, 1);
        r1 += __shfl_xor_sync(0xffffffffu, r1, 2);
        l0 = l0 * c0 + r0;  m0 = nm0;
        l1 = l1 * c1 + r1;  m1 = nm1;
        #pragma unroll
        for (int f = 0; f < 8; f++) {
            o[f][0] *= c0; o[f][1] *= c0;
            o[f][2] *= c1; o[f][3] *= c1;
        }

        uint32_t ph[4][4], pl[4][4];
        #pragma unroll
        for (int j = 0; j < 4; j++) {
            split_pack(s[2 * j][0],     s[2 * j][1],     ph[j][0], pl[j][0]);
            split_pack(s[2 * j][2],     s[2 * j][3],     ph[j][1], pl[j][1]);
            split_pack(s[2 * j + 1][0], s[2 * j + 1][1], ph[j][2], pl[j][2]);
            split_pack(s[2 * j + 1][2], s[2 * j + 1][3], ph[j][3], pl[j][3]);
        }

        #pragma unroll
        for (int ks = 0; ks < 4; ks++) {
            #pragma unroll
            for (int np = 0; np < 4; np++) {
                uint32_t vbh[4], vbl[4];
                const uint32_t va = sV + (ks * 16 + ar) * RSF + np * 32 + ac;
                ldsm_x4_t(vbh, va);
                ldsm_x4_t(vbl, va + KVT);
                #pragma unroll
                for (int hf = 0; hf < 2; hf++)
                    mma16816(o[np * 2 + hf], ph[ks], vbh + 2 * hf);
                #pragma unroll
                for (int hf = 0; hf < 2; hf++)
                    mma16816(o[np * 2 + hf], ph[ks], vbl + 2 * hf);
                #pragma unroll
                for (int hf = 0; hf < 2; hf++)
                    mma16816(o[np * 2 + hf], pl[ks], vbh + 2 * hf);
            }
        }

        slot = (slot + 1 > 2) ? 0 : (slot + 1);
        nslot = (nslot + 1 > 2) ? 0 : (nslot + 1);
    }

    const float i0 = 1.0f / l0;
    const float i1 = 1.0f / l1;
    const size_t row0 = (size_t)(b * SEQ + qi * 128 + wm * 16 + (lane >> 2));
    const int colb = (int)hoff + (lane & 3) * 2;
    #pragma unroll
    for (int f = 0; f < 8; f++) {
        const size_t off0 = row0 * DMODEL + colb + f * 8;
        const size_t off1 = (row0 + 8) * DMODEL + colb + f * 8;
        uint32_t h01, l01, h23, l23;
        split_pack(o[f][0] * i0, o[f][1] * i0, h01, l01);
        split_pack(o[f][2] * i1, o[f][3] * i1, h23, l23);
        *reinterpret_cast<uint32_t*>(&Oh[off0]) = h01;
        *reinterpret_cast<uint32_t*>(&Ol[off0]) = l01;
        *reinterpret_cast<uint32_t*>(&Oh[off1]) = h23;
        *reinterpret_cast<uint32_t*>(&Ol[off1]) = l23;
    }
#undef LOAD_KV
}

// ---------------- launch --------------------------------------------------
extern "C" void kernel_launch(void* const* d_in, const int* in_sizes, int n_in,
                              void* d_out, int out_size) {
    const float* q   = (const float*)d_in[0];
    const float* k   = (const float*)d_in[1];
    const float* v   = (const float*)d_in[2];
    // d_in[3] = mask (deterministic causal tril) — handled analytically
    const float* w_q = (const float*)d_in[4];
    const float* w_k = (const float*)d_in[5];
    const float* w_v = (const float*)d_in[6];
    const float* w_o = (const float*)d_in[7];
    float* out = (float*)d_out;

    __nv_bfloat16 *ah, *al, *bh, *bl, *ch, *cl;
    __nv_bfloat16 *qh, *ql, *kh, *kl, *vh, *vl, *wh, *wl;
    cudaGetSymbolAddress((void**)&ah, g_ah);
    cudaGetSymbolAddress((void**)&al, g_al);
    cudaGetSymbolAddress((void**)&bh, g_bh);
    cudaGetSymbolAddress((void**)&bl, g_bl);
    cudaGetSymbolAddress((void**)&ch, g_ch);
    cudaGetSymbolAddress((void**)&cl, g_cl);
    cudaGetSymbolAddress((void**)&qh, g_qh);
    cudaGetSymbolAddress((void**)&ql, g_ql);
    cudaGetSymbolAddress((void**)&kh, g_kh);
    cudaGetSymbolAddress((void**)&kl, g_kl);
    cudaGetSymbolAddress((void**)&vh, g_vh);
    cudaGetSymbolAddress((void**)&vl, g_vl);
    cudaGetSymbolAddress((void**)&wh, g_wh);
    cudaGetSymbolAddress((void**)&wl, g_wl);

    cudaFuncSetAttribute(mma_gemm_qkv,
                         cudaFuncAttributeMaxDynamicSharedMemorySize, GSMEM);
    cudaFuncSetAttribute(mma_gemm_bt,
                         cudaFuncAttributeMaxDynamicSharedMemorySize, GSMEM2);
    cudaFuncSetAttribute(flash_mma_kernel,
                         cudaFuncAttributeMaxDynamicSharedMemorySize,
                         FLASH_SMEM);

    const int nA4 = MROWS * DMODEL / 4;   // 1048576
    const int nW4 = DMODEL * DMODEL / 4;  // 262144
    const size_t WN = (size_t)DMODEL * DMODEL;

    // all splits in ONE launch (y=0..2 acts, y=3..6 weights)
    cvt_split_all<<<dim3(nA4 / 256, 7), 256>>>(
        (const float4*)q, (const float4*)k, (const float4*)v,
        (const float4*)w_q, (const float4*)w_k, (const float4*)w_v,
        (const float4*)w_o,
        (uint2*)ah, (uint2*)al, (uint2*)bh, (uint2*)bl, (uint2*)ch, (uint2*)cl,
        (uint2*)wh, (uint2*)wl, nA4, nW4);

    // fused Q/K/V projections: 128x128 tiles, 2 CTAs/SM (measured best)
    dim3 qkvgrid(DMODEL / 128, MROWS / 128, 3);  // (8, 32, 3)
    mma_gemm_qkv<<<qkvgrid, 256, GSMEM>>>(ah, al, bh, bl, ch, cl, wh, wl,
                                          qh, ql, kh, kl, vh, vl);

    // flash attention: R10/R15 best configuration
    dim3 agrid(SEQ / 128, NHEAD, BATCH);  // (16, 16, 2)
    flash_mma_kernel<<<agrid, 256, FLASH_SMEM>>>(qh, ql, kh, kl, vh, vl, ah, al);

    // output projection: 256x128 tiles (measured best for this grid size)
    dim3 ggrid(DMODEL / 128, MROWS / 256);  // (8, 16) = 128 CTAs
    mma_gemm_bt<<<ggrid, 256, GSMEM2>>>(ah, al, wh + 3 * WN, wl + 3 * WN, out);
}